// round 3
// baseline (speedup 1.0000x reference)
#include <cuda_runtime.h>
#include <cstdint>

#define NRES 128
#define TT 8   // frames (fixed by problem shape)

// ---------------- device-global scratch (no allocations allowed) ----------------
__device__ float  g_tf[64];          // target_f per (b,t)
__device__ float  g_fw[64];          // fw per (b,t)
__device__ float  g_W[8];            // sum_t fw per b
__device__ float  g_tfsum;           // total target count
__device__ float  g_nvalid[8];       // valid atom count per b
__device__ float  g_struct_pf[64];   // per-(b,t) weighted sq-err sum
__device__ double g_lddt_score;      // sum of sigmoid-sums over masked i<j pairs
__device__ double g_lddt_cnt;        // count of masked i<j frame-pairs
__device__ double g_bond_num;
__device__ double g_bond_den;
__device__ float  g_res_sum[8 * NRES];
__device__ float  g_res_cnt[8 * NRES];

// ---------------- helpers ----------------
__device__ __forceinline__ float blockReduceSum(float v) {
    __shared__ float sh[32];
    int lane = threadIdx.x & 31, wid = threadIdx.x >> 5;
#pragma unroll
    for (int o = 16; o; o >>= 1) v += __shfl_xor_sync(0xffffffffu, v, o);
    __syncthreads();                     // protect sh across repeated calls
    if (lane == 0) sh[wid] = v;
    __syncthreads();
    int nw = (blockDim.x + 31) >> 5;
    v = (lane < nw) ? sh[lane] : 0.f;
#pragma unroll
    for (int o = 16; o; o >>= 1) v += __shfl_xor_sync(0xffffffffu, v, o);
    return v;   // total available in all threads
}

// ---------------- kernel 0: init / zero accumulators ----------------
__global__ void init_kernel(const int* __restrict__ cond,
                            const int* __restrict__ am,
                            const int* __restrict__ om,
                            int B, int T, int M) {
    int tid = threadIdx.x;
    if (tid == 0) { g_lddt_score = 0.0; g_lddt_cnt = 0.0; g_bond_num = 0.0; g_bond_den = 0.0; }
    for (int i = tid; i < B * NRES; i += blockDim.x) { g_res_sum[i] = 0.f; g_res_cnt[i] = 0.f; }
    for (int i = tid; i < B * T; i += blockDim.x)    { g_struct_pf[i] = 0.f; }

    __shared__ float sv[8];
    if (tid < 8) sv[tid] = 0.f;
    __syncthreads();
    for (int i = tid; i < B * M; i += blockDim.x) {
        if (am[i] && om[i]) atomicAdd(&sv[i / M], 1.f);
    }
    __syncthreads();
    if (tid < B) g_nvalid[tid] = sv[tid];

    if (tid == 0) {
        float tot = 0.f;
        for (int b = 0; b < B; b++) {
            float s = 0.f;
            for (int t = 0; t < T; t++) {
                float tf = cond[b * T + t] ? 0.f : 1.f;
                g_tf[b * T + t] = tf;
                s += tf;
            }
            tot += s;
            float denom = fmaxf(s, 1.f);
            float W = 0.f;
            for (int t = 0; t < T; t++) {
                float f = g_tf[b * T + t] / denom;
                g_fw[b * T + t] = f;
                W += f;
            }
            g_W[b] = W;
        }
        g_tfsum = tot;
    }
}

// ---------------- kernel 1: fused pairwise kernel (lDDT + flex) ----------------
// 32x32 atom tiles over i<j upper triangle; 256 threads, 4 (ii,jj) pairs each.
__global__ void __launch_bounds__(256)
pair_kernel(const float* __restrict__ xp, const float* __restrict__ xg,
            const int* __restrict__ am, const int* __restrict__ om,
            const int* __restrict__ resid,
            int B, int M, int ntiles, int tilepairs) {
    __shared__ float spi[TT][32][3], sgi[TT][32][3], spj[TT][32][3], sgj[TT][32][3];
    __shared__ float s_tf[TT], s_fw[TT];
    __shared__ int   s_ri[32], s_rj[32];
    __shared__ float s_vi[32], s_vj[32];
    __shared__ float s_W;

    int b = blockIdx.x / tilepairs;
    int p = blockIdx.x % tilepairs;
    int ti = 0, rem = p;
    while (rem >= ntiles - ti) { rem -= ntiles - ti; ti++; }
    int tj = ti + rem;
    int tid = threadIdx.x;

    // stage coords: 768 floats per array (8 frames x 32 atoms x 3)
    for (int e = tid; e < TT * 32 * 3; e += 256) {
        int t = e / 96, r = e % 96, a = r / 3, d = r % 3;
        int gi = ti * 32 + a, gj = tj * 32 + a;
        long oi = (((long)(b * TT + t)) * M + gi) * 3 + d;
        long oj = (((long)(b * TT + t)) * M + gj) * 3 + d;
        spi[t][a][d] = xp[oi]; sgi[t][a][d] = xg[oi];
        spj[t][a][d] = xp[oj]; sgj[t][a][d] = xg[oj];
    }
    if (tid < 32) {
        int gi = ti * 32 + tid, gj = tj * 32 + tid;
        s_vi[tid] = (am[b * M + gi] && om[b * M + gi]) ? 1.f : 0.f;
        s_vj[tid] = (am[b * M + gj] && om[b * M + gj]) ? 1.f : 0.f;
        s_ri[tid] = resid[b * M + gi];
        s_rj[tid] = resid[b * M + gj];
    }
    if (tid < TT) { s_tf[tid] = g_tf[b * TT + tid]; s_fw[tid] = g_fw[b * TT + tid]; }
    if (tid == 0) s_W = g_W[b];
    __syncthreads();

    int ii = tid >> 3, jg = tid & 7;
    int gi = ti * 32 + ii;
    float vi = s_vi[ii];
    int   ri = s_ri[ii];

    float sc = 0.f, cn = 0.f;
    float e1p[4] = {0, 0, 0, 0}, e2p[4] = {0, 0, 0, 0};
    float e1g[4] = {0, 0, 0, 0}, e2g[4] = {0, 0, 0, 0};
    bool  lok[4], same[4];
#pragma unroll
    for (int k = 0; k < 4; k++) {
        int jj = jg * 4 + k, gj = tj * 32 + jj;
        bool lt = gi < gj;
        bool vp = lt && (vi != 0.f) && (s_vj[jj] != 0.f);
        lok[k]  = vp;
        same[k] = vp && (ri == s_rj[jj]);
    }

#pragma unroll
    for (int t = 0; t < TT; t++) {
        float a0 = spi[t][ii][0], a1 = spi[t][ii][1], a2 = spi[t][ii][2];
        float b0 = sgi[t][ii][0], b1 = sgi[t][ii][1], b2 = sgi[t][ii][2];
        float tf = s_tf[t], fw = s_fw[t];
#pragma unroll
        for (int k = 0; k < 4; k++) {
            int jj = jg * 4 + k;
            float d0 = a0 - spj[t][jj][0];
            float d1 = a1 - spj[t][jj][1];
            float d2 = a2 - spj[t][jj][2];
            float dp = sqrtf(fmaxf(fmaf(d0, d0, fmaf(d1, d1, d2 * d2)), 1e-12f));
            float f0 = b0 - sgj[t][jj][0];
            float f1 = b1 - sgj[t][jj][1];
            float f2 = b2 - sgj[t][jj][2];
            float dg = sqrtf(fmaxf(fmaf(f0, f0, fmaf(f1, f1, f2 * f2)), 1e-12f));

            // lDDT: sum_k sigmoid(th_k - |dp-dg|) with one exp + one fast div
            if (lok[k] && (tf != 0.f) && (dg < 15.f)) {
                float diff = fminf(fabsf(dp - dg), 20.f);
                float ex = __expf(diff);
                float u0 = fmaf(ex, 0.60653066f, 1.f);   // e^{-0.5}
                float u1 = fmaf(ex, 0.36787944f, 1.f);   // e^{-1}
                float u2 = fmaf(ex, 0.13533528f, 1.f);   // e^{-2}
                float u3 = fmaf(ex, 0.018315639f, 1.f);  // e^{-4}
                float p01 = u0 * u1, p23 = u2 * u3;
                float num = p23 * (u0 + u1) + p01 * (u2 + u3);
                sc += __fdividef(num, p01 * p23);
                cn += 1.f;
            }
            // flex moments (same-residue pairs only; sparse)
            if (same[k]) {
                e1p[k] = fmaf(fw, dp, e1p[k]);
                e2p[k] = fmaf(fw, dp * dp, e2p[k]);
                e1g[k] = fmaf(fw, dg, e1g[k]);
                e2g[k] = fmaf(fw, dg * dg, e2g[k]);
            }
        }
    }

    // flex finalize per pair -> per-residue segment atomics
#pragma unroll
    for (int k = 0; k < 4; k++) {
        if (same[k]) {
            float W = s_W;
            float mp = e1p[k], mg = e1g[k];
            float vp_ = fmaxf(e2p[k] - mp * mp * (2.f - W), 0.f);
            float vg_ = fmaxf(e2g[k] - mg * mg * (2.f - W), 0.f);
            float sp = sqrtf(vp_ + 1e-8f);
            float sg = sqrtf(vg_ + 1e-8f);
            float dq = (sp - sg) * (sp - sg);
            int r = min(max(ri, 0), NRES - 1);
            atomicAdd(&g_res_sum[b * NRES + r], dq);
            atomicAdd(&g_res_cnt[b * NRES + r], 1.f);
        }
    }

    float tsc = blockReduceSum(sc);
    float tcn = blockReduceSum(cn);
    if (tid == 0) {
        atomicAdd(&g_lddt_score, (double)tsc);
        atomicAdd(&g_lddt_cnt, (double)tcn);
    }
}

// ---------------- kernel 2: structure loss per-frame sums ----------------
__global__ void struct_kernel(const float* __restrict__ xp, const float* __restrict__ xg,
                              const int* __restrict__ am, const int* __restrict__ om,
                              const int* __restrict__ mol, int B, int T, int M) {
    int bt = blockIdx.x;
    int b = bt / T;
    const float* P = xp + (long)bt * M * 3;
    const float* G = xg + (long)bt * M * 3;
    float acc = 0.f;
    for (int m = threadIdx.x; m < M; m += blockDim.x) {
        float d0 = P[m * 3 + 0] - G[m * 3 + 0];
        float d1 = P[m * 3 + 1] - G[m * 3 + 1];
        float d2 = P[m * 3 + 2] - G[m * 3 + 2];
        float sq = fmaf(d0, d0, fmaf(d1, d1, d2 * d2));
        bool v = am[b * M + m] && om[b * M + m];
        int mt = mol[b * M + m];
        float w = v ? ((mt == 0) ? 1.f : (mt == 3) ? 10.f : 5.f) : 0.f;
        acc += sq * w;
    }
    acc = blockReduceSum(acc);
    if (threadIdx.x == 0) g_struct_pf[bt] = acc;
}

// ---------------- kernel 3: bond loss ----------------
__global__ void bond_kernel(const float* __restrict__ xp, const float* __restrict__ blen,
                            const int* __restrict__ bidx, const int* __restrict__ bmask,
                            int B, int T, int M, int NB) {
    int idx = blockIdx.x * blockDim.x + threadIdx.x;
    float num = 0.f, den = 0.f;
    if (idx < B * NB) {
        int b = idx / NB;
        int i = bidx[idx * 2 + 0];
        int j = bidx[idx * 2 + 1];
        float bl = blen[idx];
        if (bmask[idx]) {
            for (int t = 0; t < T; t++) {
                const float* base = xp + ((long)(b * T + t)) * M * 3;
                float d0 = base[i * 3 + 0] - base[j * 3 + 0];
                float d1 = base[i * 3 + 1] - base[j * 3 + 1];
                float d2 = base[i * 3 + 2] - base[j * 3 + 2];
                float pl = sqrtf(fmaf(d0, d0, fmaf(d1, d1, d2 * d2)) + 1e-12f);
                float df = pl - bl;
                float tf = g_tf[b * T + t];
                num += df * df * tf;
                den += tf;
            }
        }
    }
    num = blockReduceSum(num);
    den = blockReduceSum(den);
    if (threadIdx.x == 0) {
        atomicAdd(&g_bond_num, (double)num);
        atomicAdd(&g_bond_den, (double)den);
    }
}

// ---------------- kernel 4: finalize ----------------
__global__ void finalize_kernel(const float* __restrict__ sigma, float* __restrict__ out,
                                int B, int T) {
    int tid = threadIdx.x;
    float lsum = 0.f, lok = 0.f;
    for (int i = tid; i < B * NRES; i += blockDim.x) {
        float c = g_res_cnt[i];
        if (c > 0.f) { lsum += g_res_sum[i] / c; lok += 1.f; }
    }
    float t1 = blockReduceSum(lsum);
    float t2 = blockReduceSum(lok);

    float ssum = 0.f;
    for (int i = tid; i < B * T; i += blockDim.x) {
        int b = i / T;
        float s = sigma[i];
        float tf = g_tf[i];
        float den = s * 16.f + 1e-8f;
        float ew = (s * s + 256.f) / (den * den) * tf;
        ssum += ew * g_struct_pf[i] / fmaxf(g_nvalid[b], 1.f);
    }
    float t3 = blockReduceSum(ssum);

    if (tid == 0) {
        float l_local  = t1 / fmaxf(t2, 1.f);
        float l_struct = t3 / fmaxf(g_tfsum, 1.f);
        double cnt = g_lddt_cnt;
        float l_lddt = 1.f - (float)((g_lddt_score * 0.25) / (cnt > 1.0 ? cnt : 1.0));
        double bd = g_bond_den;
        float l_bond = (float)(g_bond_num / (bd > 1.0 ? bd : 1.0));
        out[0] = l_struct + l_bond + l_lddt + 4.f * l_local;
    }
}

// ---------------- launch ----------------
extern "C" void kernel_launch(void* const* d_in, const int* in_sizes, int n_in,
                              void* d_out, int out_size) {
    const float* xp    = (const float*)d_in[0];
    const float* xg    = (const float*)d_in[1];
    const float* sigma = (const float*)d_in[2];
    const float* blen  = (const float*)d_in[3];
    const int*   cond  = (const int*)d_in[4];
    const int*   am    = (const int*)d_in[5];
    const int*   om    = (const int*)d_in[6];
    const int*   mol   = (const int*)d_in[7];
    const int*   resid = (const int*)d_in[8];
    const int*   bidx  = (const int*)d_in[9];
    const int*   bmask = (const int*)d_in[10];

    int BT = in_sizes[2];                 // B*T
    int M  = in_sizes[0] / (BT * 3);      // atoms
    int B  = in_sizes[5] / M;             // batch
    int T  = BT / B;                      // frames (== 8)
    int NB = in_sizes[10] / B;            // bonds

    init_kernel<<<1, 256>>>(cond, am, om, B, T, M);

    int ntiles = M / 32;
    int tilepairs = ntiles * (ntiles + 1) / 2;
    pair_kernel<<<B * tilepairs, 256>>>(xp, xg, am, om, resid, B, M, ntiles, tilepairs);

    struct_kernel<<<B * T, 256>>>(xp, xg, am, om, mol, B, T, M);
    bond_kernel<<<(B * NB + 255) / 256, 256>>>(xp, blen, bidx, bmask, B, T, M, NB);
    finalize_kernel<<<1, 256>>>(sigma, (float*)d_out, B, T);
}

// round 4
// speedup vs baseline: 1.1670x; 1.1670x over previous
#include <cuda_runtime.h>
#include <cstdint>

#define NRES 128
#define TT 8   // frames (fixed by problem shape)

// ---------------- device-global scratch (no allocations allowed) ----------------
__device__ float  g_nvalid[8];       // valid atom count per b
__device__ float  g_struct_pf[64];   // per-(b,t) weighted sq-err sum
__device__ double g_lddt_score;      // sum of sigmoid-sums over masked i<j pairs
__device__ double g_lddt_cnt;        // count of masked i<j frame-pairs
__device__ double g_bond_num;
__device__ double g_bond_den;
__device__ float  g_res_sum[8 * NRES];
__device__ float  g_res_cnt[8 * NRES];

// ---------------- helpers ----------------
__device__ __forceinline__ float fsqrt_approx(float x) {
    float r;
    asm("sqrt.approx.f32 %0, %1;" : "=f"(r) : "f"(x));
    return r;
}

__device__ __forceinline__ float blockReduceSum(float v) {
    __shared__ float sh[32];
    int lane = threadIdx.x & 31, wid = threadIdx.x >> 5;
#pragma unroll
    for (int o = 16; o; o >>= 1) v += __shfl_xor_sync(0xffffffffu, v, o);
    __syncthreads();
    if (lane == 0) sh[wid] = v;
    __syncthreads();
    int nw = (blockDim.x + 31) >> 5;
    v = (lane < nw) ? sh[lane] : 0.f;
#pragma unroll
    for (int o = 16; o; o >>= 1) v += __shfl_xor_sync(0xffffffffu, v, o);
    return v;
}

// ---------------- kernel 0: zero accumulators + valid-atom counts ----------------
__global__ void init_kernel(const int* __restrict__ am, const int* __restrict__ om,
                            int B, int M) {
    int tid = threadIdx.x;
    if (tid == 0) { g_lddt_score = 0.0; g_lddt_cnt = 0.0; g_bond_num = 0.0; g_bond_den = 0.0; }
    for (int i = tid; i < B * NRES; i += blockDim.x) { g_res_sum[i] = 0.f; g_res_cnt[i] = 0.f; }

    __shared__ float sv[8];
    if (tid < 8) sv[tid] = 0.f;
    __syncthreads();
    for (int i = tid; i < B * M; i += blockDim.x) {
        if (am[i] && om[i]) atomicAdd(&sv[i / M], 1.f);
    }
    __syncthreads();
    if (tid < B) g_nvalid[tid] = sv[tid];
}

// ---------------- mega kernel: pair (lDDT+flex) + struct + bond, role by block ----------------
__global__ void __launch_bounds__(256)
mega_kernel(const float* __restrict__ xp, const float* __restrict__ xg,
            const int* __restrict__ cond,
            const int* __restrict__ am, const int* __restrict__ om,
            const int* __restrict__ mol, const int* __restrict__ resid,
            const float* __restrict__ blen, const int* __restrict__ bidx,
            const int* __restrict__ bmask,
            int B, int T, int M, int NB,
            int ntiles, int tilepairs, int nPair, int nStruct) {
    int blk = blockIdx.x;
    int tid = threadIdx.x;

    if (blk < nPair) {
        // ================= pair role: 32x32 atom tile, i<j upper triangle =================
        __shared__ float spi[TT][32][3], sgi[TT][32][3], spj[TT][32][3], sgj[TT][32][3];
        __shared__ float s_tf[TT], s_fw[TT];
        __shared__ int   s_ri[32], s_rj[32];
        __shared__ float s_vi[32], s_vj[32];
        __shared__ float s_W;

        int b = blk / tilepairs;
        int p = blk % tilepairs;
        int ti = 0, rem = p;
        while (rem >= ntiles - ti) { rem -= ntiles - ti; ti++; }
        int tj = ti + rem;

        // per-block frame weights straight from cond (no init dependency)
        if (tid == 0) {
            float s = 0.f;
            for (int t = 0; t < TT; t++) {
                float tf = cond[b * TT + t] ? 0.f : 1.f;
                s_tf[t] = tf; s += tf;
            }
            float denom = fmaxf(s, 1.f);
            float W = 0.f;
            for (int t = 0; t < TT; t++) { float f = s_tf[t] / denom; s_fw[t] = f; W += f; }
            s_W = W;
        }

        for (int e = tid; e < TT * 32 * 3; e += 256) {
            int t = e / 96, r = e % 96, a = r / 3, d = r % 3;
            int gi = ti * 32 + a, gj = tj * 32 + a;
            long oi = (((long)(b * TT + t)) * M + gi) * 3 + d;
            long oj = (((long)(b * TT + t)) * M + gj) * 3 + d;
            spi[t][a][d] = xp[oi]; sgi[t][a][d] = xg[oi];
            spj[t][a][d] = xp[oj]; sgj[t][a][d] = xg[oj];
        }
        if (tid < 32) {
            int gi = ti * 32 + tid, gj = tj * 32 + tid;
            s_vi[tid] = (am[b * M + gi] && om[b * M + gi]) ? 1.f : 0.f;
            s_vj[tid] = (am[b * M + gj] && om[b * M + gj]) ? 1.f : 0.f;
            s_ri[tid] = resid[b * M + gi];
            s_rj[tid] = resid[b * M + gj];
        }
        __syncthreads();

        int ii = tid >> 3, jg = tid & 7;
        int gi = ti * 32 + ii;
        float vi = s_vi[ii];
        int   ri = s_ri[ii];

        float sc = 0.f, cn = 0.f;
        float e1p[4] = {0, 0, 0, 0}, e2p[4] = {0, 0, 0, 0};
        float e1g[4] = {0, 0, 0, 0}, e2g[4] = {0, 0, 0, 0};
        bool  lok[4], same[4];
#pragma unroll
        for (int k = 0; k < 4; k++) {
            int jj = jg * 4 + k, gj = tj * 32 + jj;
            bool lt = gi < gj;
            bool vp = lt && (vi != 0.f) && (s_vj[jj] != 0.f);
            lok[k]  = vp;
            same[k] = vp && (ri == s_rj[jj]);
        }

#pragma unroll
        for (int t = 0; t < TT; t++) {
            float a0 = spi[t][ii][0], a1 = spi[t][ii][1], a2 = spi[t][ii][2];
            float c0 = sgi[t][ii][0], c1 = sgi[t][ii][1], c2 = sgi[t][ii][2];
            float tf = s_tf[t], fw = s_fw[t];
#pragma unroll
            for (int k = 0; k < 4; k++) {
                int jj = jg * 4 + k;
                float d0 = a0 - spj[t][jj][0];
                float d1 = a1 - spj[t][jj][1];
                float d2 = a2 - spj[t][jj][2];
                float dp = fsqrt_approx(fmaxf(fmaf(d0, d0, fmaf(d1, d1, d2 * d2)), 1e-12f));
                float f0 = c0 - sgj[t][jj][0];
                float f1 = c1 - sgj[t][jj][1];
                float f2 = c2 - sgj[t][jj][2];
                float dg = fsqrt_approx(fmaxf(fmaf(f0, f0, fmaf(f1, f1, f2 * f2)), 1e-12f));

                // lDDT: sum_k sigmoid(th_k - |dp-dg|) via one exp + one fast div
                if (lok[k] && (tf != 0.f) && (dg < 15.f)) {
                    float diff = fminf(fabsf(dp - dg), 20.f);
                    float ex = __expf(diff);
                    float u0 = fmaf(ex, 0.60653066f, 1.f);   // e^{-0.5}
                    float u1 = fmaf(ex, 0.36787944f, 1.f);   // e^{-1}
                    float u2 = fmaf(ex, 0.13533528f, 1.f);   // e^{-2}
                    float u3 = fmaf(ex, 0.018315639f, 1.f);  // e^{-4}
                    float p01 = u0 * u1, p23 = u2 * u3;
                    float num = p23 * (u0 + u1) + p01 * (u2 + u3);
                    sc += __fdividef(num, p01 * p23);
                    cn += 1.f;
                }
                if (same[k]) {
                    e1p[k] = fmaf(fw, dp, e1p[k]);
                    e2p[k] = fmaf(fw, dp * dp, e2p[k]);
                    e1g[k] = fmaf(fw, dg, e1g[k]);
                    e2g[k] = fmaf(fw, dg * dg, e2g[k]);
                }
            }
        }

#pragma unroll
        for (int k = 0; k < 4; k++) {
            if (same[k]) {
                float W = s_W;
                float mp = e1p[k], mg = e1g[k];
                float vp_ = fmaxf(e2p[k] - mp * mp * (2.f - W), 0.f);
                float vg_ = fmaxf(e2g[k] - mg * mg * (2.f - W), 0.f);
                float sp = fsqrt_approx(vp_ + 1e-8f);
                float sg = fsqrt_approx(vg_ + 1e-8f);
                float dq = (sp - sg) * (sp - sg);
                int r = min(max(ri, 0), NRES - 1);
                atomicAdd(&g_res_sum[b * NRES + r], dq);
                atomicAdd(&g_res_cnt[b * NRES + r], 1.f);
            }
        }

        float tsc = blockReduceSum(sc);
        float tcn = blockReduceSum(cn);
        if (tid == 0) {
            atomicAdd(&g_lddt_score, (double)tsc);
            atomicAdd(&g_lddt_cnt, (double)tcn);
        }
    } else if (blk < nPair + nStruct) {
        // ================= struct role: one block per (b,t) =================
        int bt = blk - nPair;
        int b = bt / T;
        const float* P = xp + (long)bt * M * 3;
        const float* G = xg + (long)bt * M * 3;
        float acc = 0.f;
        for (int m = tid; m < M; m += 256) {
            float d0 = P[m * 3 + 0] - G[m * 3 + 0];
            float d1 = P[m * 3 + 1] - G[m * 3 + 1];
            float d2 = P[m * 3 + 2] - G[m * 3 + 2];
            float sq = fmaf(d0, d0, fmaf(d1, d1, d2 * d2));
            bool v = am[b * M + m] && om[b * M + m];
            int mt = mol[b * M + m];
            float w = v ? ((mt == 0) ? 1.f : (mt == 3) ? 10.f : 5.f) : 0.f;
            acc += sq * w;
        }
        acc = blockReduceSum(acc);
        if (tid == 0) g_struct_pf[bt] = acc;
    } else {
        // ================= bond role: one thread per (b, bond, frame) =================
        int g = (blk - nPair - nStruct) * 256 + tid;
        float num = 0.f, den = 0.f;
        if (g < B * NB * T) {
            int b  = g / (NB * T);
            int r  = g % (NB * T);
            int nb = r / T;
            int t  = r % T;
            int bond = b * NB + nb;
            if (bmask[bond]) {
                float tf = cond[b * T + t] ? 0.f : 1.f;
                int i = bidx[bond * 2 + 0];
                int j = bidx[bond * 2 + 1];
                const float* base = xp + ((long)(b * T + t)) * M * 3;
                float d0 = base[i * 3 + 0] - base[j * 3 + 0];
                float d1 = base[i * 3 + 1] - base[j * 3 + 1];
                float d2 = base[i * 3 + 2] - base[j * 3 + 2];
                float pl = fsqrt_approx(fmaf(d0, d0, fmaf(d1, d1, d2 * d2)) + 1e-12f);
                float df = pl - blen[bond];
                num = df * df * tf;
                den = tf;
            }
        }
        num = blockReduceSum(num);
        den = blockReduceSum(den);
        if (tid == 0) {
            atomicAdd(&g_bond_num, (double)num);
            atomicAdd(&g_bond_den, (double)den);
        }
    }
}

// ---------------- finalize ----------------
__global__ void finalize_kernel(const float* __restrict__ sigma, const int* __restrict__ cond,
                                float* __restrict__ out, int B, int T) {
    int tid = threadIdx.x;
    float lsum = 0.f, lok = 0.f;
    for (int i = tid; i < B * NRES; i += blockDim.x) {
        float c = g_res_cnt[i];
        if (c > 0.f) { lsum += g_res_sum[i] / c; lok += 1.f; }
    }
    float t1 = blockReduceSum(lsum);
    float t2 = blockReduceSum(lok);

    float ssum = 0.f, tfs = 0.f;
    for (int i = tid; i < B * T; i += blockDim.x) {
        int b = i / T;
        float s = sigma[i];
        float tf = cond[i] ? 0.f : 1.f;
        tfs += tf;
        float den = s * 16.f + 1e-8f;
        float ew = (s * s + 256.f) / (den * den) * tf;
        ssum += ew * g_struct_pf[i] / fmaxf(g_nvalid[b], 1.f);
    }
    float t3 = blockReduceSum(ssum);
    float t4 = blockReduceSum(tfs);

    if (tid == 0) {
        float l_local  = t1 / fmaxf(t2, 1.f);
        float l_struct = t3 / fmaxf(t4, 1.f);
        double cnt = g_lddt_cnt;
        float l_lddt = 1.f - (float)((g_lddt_score * 0.25) / (cnt > 1.0 ? cnt : 1.0));
        double bd = g_bond_den;
        float l_bond = (float)(g_bond_num / (bd > 1.0 ? bd : 1.0));
        out[0] = l_struct + l_bond + l_lddt + 4.f * l_local;
    }
}

// ---------------- launch ----------------
extern "C" void kernel_launch(void* const* d_in, const int* in_sizes, int n_in,
                              void* d_out, int out_size) {
    const float* xp    = (const float*)d_in[0];
    const float* xg    = (const float*)d_in[1];
    const float* sigma = (const float*)d_in[2];
    const float* blen  = (const float*)d_in[3];
    const int*   cond  = (const int*)d_in[4];
    const int*   am    = (const int*)d_in[5];
    const int*   om    = (const int*)d_in[6];
    const int*   mol   = (const int*)d_in[7];
    const int*   resid = (const int*)d_in[8];
    const int*   bidx  = (const int*)d_in[9];
    const int*   bmask = (const int*)d_in[10];

    int BT = in_sizes[2];                 // B*T
    int M  = in_sizes[0] / (BT * 3);      // atoms
    int B  = in_sizes[5] / M;             // batch
    int T  = BT / B;                      // frames (== 8)
    int NB = in_sizes[10] / B;            // bonds

    init_kernel<<<1, 256>>>(am, om, B, M);

    int ntiles = M / 32;
    int tilepairs = ntiles * (ntiles + 1) / 2;
    int nPair   = B * tilepairs;
    int nStruct = B * T;
    int nBond   = (B * NB * T + 255) / 256;
    mega_kernel<<<nPair + nStruct + nBond, 256>>>(
        xp, xg, cond, am, om, mol, resid, blen, bidx, bmask,
        B, T, M, NB, ntiles, tilepairs, nPair, nStruct);

    finalize_kernel<<<1, 256>>>(sigma, cond, (float*)d_out, B, T);
}

// round 5
// speedup vs baseline: 3.2194x; 2.7587x over previous
#include <cuda_runtime.h>
#include <cstdint>

#define NRES 128
#define TT 8   // frames (fixed by problem shape)

// ---------------- device-global scratch (zero-initialized at load; finalize
// restores the all-zero invariant after every call -> deterministic) ----------------
__device__ float  g_struct_pf[64];   // per-(b,t) weighted sq-err sum / n_valid
__device__ double g_lddt_score;      // sum of sigmoid-sums over masked i<j pairs
__device__ double g_lddt_cnt;        // count of masked i<j frame-pairs
__device__ double g_bond_num;
__device__ double g_bond_den;
__device__ float  g_res_sum[8 * NRES];
__device__ float  g_res_cnt[8 * NRES];

// ---------------- helpers ----------------
__device__ __forceinline__ float fsqrt_approx(float x) {
    float r;
    asm("sqrt.approx.f32 %0, %1;" : "=f"(r) : "f"(x));
    return r;
}

__device__ __forceinline__ float blockReduceSum(float v) {
    __shared__ float sh[32];
    int lane = threadIdx.x & 31, wid = threadIdx.x >> 5;
#pragma unroll
    for (int o = 16; o; o >>= 1) v += __shfl_xor_sync(0xffffffffu, v, o);
    __syncthreads();
    if (lane == 0) sh[wid] = v;
    __syncthreads();
    int nw = (blockDim.x + 31) >> 5;
    v = (lane < nw) ? sh[lane] : 0.f;
#pragma unroll
    for (int o = 16; o; o >>= 1) v += __shfl_xor_sync(0xffffffffu, v, o);
    return v;
}

// ---------------- mega kernel: pair (lDDT+flex) + struct + bond, role by block ----------------
__global__ void __launch_bounds__(256)
mega_kernel(const float* __restrict__ xp, const float* __restrict__ xg,
            const int* __restrict__ cond,
            const int* __restrict__ am, const int* __restrict__ om,
            const int* __restrict__ mol, const int* __restrict__ resid,
            const float* __restrict__ blen, const int* __restrict__ bidx,
            const int* __restrict__ bmask,
            int B, int T, int M, int NB,
            int ntiles, int tilepairs, int nPair, int nStruct) {
    int blk = blockIdx.x;
    int tid = threadIdx.x;

    if (blk < nPair) {
        // ================= pair role: 32x32 atom tile, i<j upper triangle =================
        __shared__ float spi[TT][32][3], sgi[TT][32][3], spj[TT][32][3], sgj[TT][32][3];
        __shared__ float s_tf[TT], s_fw[TT];
        __shared__ int   s_ri[32], s_rj[32];
        __shared__ float s_vi[32], s_vj[32];
        __shared__ float s_W;

        int b = blk / tilepairs;
        int p = blk % tilepairs;
        int ti = 0, rem = p;
        while (rem >= ntiles - ti) { rem -= ntiles - ti; ti++; }
        int tj = ti + rem;

        // per-block frame weights straight from cond (no init dependency)
        if (tid == 0) {
            float s = 0.f;
            for (int t = 0; t < TT; t++) {
                float tf = cond[b * TT + t] ? 0.f : 1.f;
                s_tf[t] = tf; s += tf;
            }
            float denom = fmaxf(s, 1.f);
            float W = 0.f;
            for (int t = 0; t < TT; t++) { float f = s_tf[t] / denom; s_fw[t] = f; W += f; }
            s_W = W;
        }

        for (int e = tid; e < TT * 32 * 3; e += 256) {
            int t = e / 96, r = e % 96, a = r / 3, d = r % 3;
            int gi = ti * 32 + a, gj = tj * 32 + a;
            long oi = (((long)(b * TT + t)) * M + gi) * 3 + d;
            long oj = (((long)(b * TT + t)) * M + gj) * 3 + d;
            spi[t][a][d] = xp[oi]; sgi[t][a][d] = xg[oi];
            spj[t][a][d] = xp[oj]; sgj[t][a][d] = xg[oj];
        }
        if (tid < 32) {
            int gi = ti * 32 + tid, gj = tj * 32 + tid;
            s_vi[tid] = (am[b * M + gi] && om[b * M + gi]) ? 1.f : 0.f;
            s_vj[tid] = (am[b * M + gj] && om[b * M + gj]) ? 1.f : 0.f;
            s_ri[tid] = resid[b * M + gi];
            s_rj[tid] = resid[b * M + gj];
        }
        __syncthreads();

        int ii = tid >> 3, jg = tid & 7;
        int gi = ti * 32 + ii;
        float vi = s_vi[ii];
        int   ri = s_ri[ii];

        float sc = 0.f, cn = 0.f;
        float e1p[4] = {0, 0, 0, 0}, e2p[4] = {0, 0, 0, 0};
        float e1g[4] = {0, 0, 0, 0}, e2g[4] = {0, 0, 0, 0};
        bool  lok[4], same[4];
#pragma unroll
        for (int k = 0; k < 4; k++) {
            int jj = jg * 4 + k, gj = tj * 32 + jj;
            bool lt = gi < gj;
            bool vp = lt && (vi != 0.f) && (s_vj[jj] != 0.f);
            lok[k]  = vp;
            same[k] = vp && (ri == s_rj[jj]);
        }

#pragma unroll
        for (int t = 0; t < TT; t++) {
            float a0 = spi[t][ii][0], a1 = spi[t][ii][1], a2 = spi[t][ii][2];
            float c0 = sgi[t][ii][0], c1 = sgi[t][ii][1], c2 = sgi[t][ii][2];
            float tf = s_tf[t], fw = s_fw[t];
#pragma unroll
            for (int k = 0; k < 4; k++) {
                int jj = jg * 4 + k;
                float d0 = a0 - spj[t][jj][0];
                float d1 = a1 - spj[t][jj][1];
                float d2 = a2 - spj[t][jj][2];
                float dp = fsqrt_approx(fmaxf(fmaf(d0, d0, fmaf(d1, d1, d2 * d2)), 1e-12f));
                float f0 = c0 - sgj[t][jj][0];
                float f1 = c1 - sgj[t][jj][1];
                float f2 = c2 - sgj[t][jj][2];
                float dg = fsqrt_approx(fmaxf(fmaf(f0, f0, fmaf(f1, f1, f2 * f2)), 1e-12f));

                // lDDT: sum_k sigmoid(th_k - |dp-dg|) via one exp + one fast div
                if (lok[k] && (tf != 0.f) && (dg < 15.f)) {
                    float diff = fminf(fabsf(dp - dg), 20.f);
                    float ex = __expf(diff);
                    float u0 = fmaf(ex, 0.60653066f, 1.f);   // e^{-0.5}
                    float u1 = fmaf(ex, 0.36787944f, 1.f);   // e^{-1}
                    float u2 = fmaf(ex, 0.13533528f, 1.f);   // e^{-2}
                    float u3 = fmaf(ex, 0.018315639f, 1.f);  // e^{-4}
                    float p01 = u0 * u1, p23 = u2 * u3;
                    float num = p23 * (u0 + u1) + p01 * (u2 + u3);
                    sc += __fdividef(num, p01 * p23);
                    cn += 1.f;
                }
                if (same[k]) {
                    e1p[k] = fmaf(fw, dp, e1p[k]);
                    e2p[k] = fmaf(fw, dp * dp, e2p[k]);
                    e1g[k] = fmaf(fw, dg, e1g[k]);
                    e2g[k] = fmaf(fw, dg * dg, e2g[k]);
                }
            }
        }

#pragma unroll
        for (int k = 0; k < 4; k++) {
            if (same[k]) {
                float W = s_W;
                float mp = e1p[k], mg = e1g[k];
                float vp_ = fmaxf(e2p[k] - mp * mp * (2.f - W), 0.f);
                float vg_ = fmaxf(e2g[k] - mg * mg * (2.f - W), 0.f);
                float sp = fsqrt_approx(vp_ + 1e-8f);
                float sg = fsqrt_approx(vg_ + 1e-8f);
                float dq = (sp - sg) * (sp - sg);
                int r = min(max(ri, 0), NRES - 1);
                atomicAdd(&g_res_sum[b * NRES + r], dq);
                atomicAdd(&g_res_cnt[b * NRES + r], 1.f);
            }
        }

        float tsc = blockReduceSum(sc);
        float tcn = blockReduceSum(cn);
        if (tid == 0) {
            atomicAdd(&g_lddt_score, (double)tsc);
            atomicAdd(&g_lddt_cnt, (double)tcn);
        }
    } else if (blk < nPair + nStruct) {
        // ================= struct role: one block per (b,t); also counts valid atoms =================
        int bt = blk - nPair;
        int b = bt / T;
        const float* P = xp + (long)bt * M * 3;
        const float* G = xg + (long)bt * M * 3;
        float acc = 0.f, vcnt = 0.f;
        for (int m = tid; m < M; m += 256) {
            float d0 = P[m * 3 + 0] - G[m * 3 + 0];
            float d1 = P[m * 3 + 1] - G[m * 3 + 1];
            float d2 = P[m * 3 + 2] - G[m * 3 + 2];
            float sq = fmaf(d0, d0, fmaf(d1, d1, d2 * d2));
            bool v = am[b * M + m] && om[b * M + m];
            int mt = mol[b * M + m];
            float w = v ? ((mt == 0) ? 1.f : (mt == 3) ? 10.f : 5.f) : 0.f;
            acc += sq * w;
            vcnt += v ? 1.f : 0.f;
        }
        acc  = blockReduceSum(acc);
        vcnt = blockReduceSum(vcnt);
        if (tid == 0) g_struct_pf[bt] = acc / fmaxf(vcnt, 1.f);
    } else {
        // ================= bond role: one thread per (b, bond, frame) =================
        int g = (blk - nPair - nStruct) * 256 + tid;
        float num = 0.f, den = 0.f;
        if (g < B * NB * T) {
            int b  = g / (NB * T);
            int r  = g % (NB * T);
            int nb = r / T;
            int t  = r % T;
            int bond = b * NB + nb;
            if (bmask[bond]) {
                float tf = cond[b * T + t] ? 0.f : 1.f;
                int i = bidx[bond * 2 + 0];
                int j = bidx[bond * 2 + 1];
                const float* base = xp + ((long)(b * T + t)) * M * 3;
                float d0 = base[i * 3 + 0] - base[j * 3 + 0];
                float d1 = base[i * 3 + 1] - base[j * 3 + 1];
                float d2 = base[i * 3 + 2] - base[j * 3 + 2];
                float pl = fsqrt_approx(fmaf(d0, d0, fmaf(d1, d1, d2 * d2)) + 1e-12f);
                float df = pl - blen[bond];
                num = df * df * tf;
                den = tf;
            }
        }
        num = blockReduceSum(num);
        den = blockReduceSum(den);
        if (tid == 0) {
            atomicAdd(&g_bond_num, (double)num);
            atomicAdd(&g_bond_den, (double)den);
        }
    }
}

// ---------------- finalize: compute output, then restore zero-state invariant ----------------
__global__ void finalize_kernel(const float* __restrict__ sigma, const int* __restrict__ cond,
                                float* __restrict__ out, int B, int T) {
    int tid = threadIdx.x;
    float lsum = 0.f, lok = 0.f;
    for (int i = tid; i < B * NRES; i += blockDim.x) {
        float c = g_res_cnt[i];
        if (c > 0.f) { lsum += g_res_sum[i] / c; lok += 1.f; }
    }
    float t1 = blockReduceSum(lsum);
    float t2 = blockReduceSum(lok);

    float ssum = 0.f, tfs = 0.f;
    for (int i = tid; i < B * T; i += blockDim.x) {
        float s = sigma[i];
        float tf = cond[i] ? 0.f : 1.f;
        tfs += tf;
        float den = s * 16.f + 1e-8f;
        float ew = (s * s + 256.f) / (den * den) * tf;
        ssum += ew * g_struct_pf[i];
    }
    float t3 = blockReduceSum(ssum);
    float t4 = blockReduceSum(tfs);

    if (tid == 0) {
        float l_local  = t1 / fmaxf(t2, 1.f);
        float l_struct = t3 / fmaxf(t4, 1.f);
        double cnt = g_lddt_cnt;
        float l_lddt = 1.f - (float)((g_lddt_score * 0.25) / (cnt > 1.0 ? cnt : 1.0));
        double bd = g_bond_den;
        float l_bond = (float)(g_bond_num / (bd > 1.0 ? bd : 1.0));
        out[0] = l_struct + l_bond + l_lddt + 4.f * l_local;
    }

    // restore the all-zero invariant for the next call (reads above are done:
    // every blockReduceSum ends with full-block __syncthreads-protected shuffles)
    __syncthreads();
    for (int i = tid; i < 8 * NRES; i += blockDim.x) { g_res_sum[i] = 0.f; g_res_cnt[i] = 0.f; }
    for (int i = tid; i < 64; i += blockDim.x)        { g_struct_pf[i] = 0.f; }
    if (tid == 0) { g_lddt_score = 0.0; g_lddt_cnt = 0.0; g_bond_num = 0.0; g_bond_den = 0.0; }
}

// ---------------- launch ----------------
extern "C" void kernel_launch(void* const* d_in, const int* in_sizes, int n_in,
                              void* d_out, int out_size) {
    const float* xp    = (const float*)d_in[0];
    const float* xg    = (const float*)d_in[1];
    const float* sigma = (const float*)d_in[2];
    const float* blen  = (const float*)d_in[3];
    const int*   cond  = (const int*)d_in[4];
    const int*   am    = (const int*)d_in[5];
    const int*   om    = (const int*)d_in[6];
    const int*   mol   = (const int*)d_in[7];
    const int*   resid = (const int*)d_in[8];
    const int*   bidx  = (const int*)d_in[9];
    const int*   bmask = (const int*)d_in[10];

    int BT = in_sizes[2];                 // B*T
    int M  = in_sizes[0] / (BT * 3);      // atoms
    int B  = in_sizes[5] / M;             // batch
    int T  = BT / B;                      // frames (== 8)
    int NB = in_sizes[10] / B;            // bonds

    int ntiles = M / 32;
    int tilepairs = ntiles * (ntiles + 1) / 2;
    int nPair   = B * tilepairs;
    int nStruct = B * T;
    int nBond   = (B * NB * T + 255) / 256;
    mega_kernel<<<nPair + nStruct + nBond, 256>>>(
        xp, xg, cond, am, om, mol, resid, blen, bidx, bmask,
        B, T, M, NB, ntiles, tilepairs, nPair, nStruct);

    finalize_kernel<<<1, 256>>>(sigma, cond, (float*)d_out, B, T);
}